// round 14
// baseline (speedup 1.0000x reference)
#include <cuda_runtime.h>
#include <cuda_bf16.h>
#include <cstdint>
#include <math.h>

// ---------------- problem constants ----------------
constexpr int Bdim = 4;
constexpr int Tdim = 96;
constexpr int Ndim = 512;
constexpr int Hdim = 128;

// ---------------- helpers ----------------
__device__ __forceinline__ uint32_t smem_u32(const void* p) {
    uint32_t a;
    asm("{ .reg .u64 t; cvta.to.shared.u64 t, %1; cvt.u32.u64 %0, t; }"
        : "=r"(a) : "l"(p));
    return a;
}

#define LDSM4(r, addr)                                                        \
    asm volatile("ldmatrix.sync.aligned.m8n8.x4.shared.b16 {%0,%1,%2,%3}, [%4];" \
                 : "=r"((r)[0]), "=r"((r)[1]), "=r"((r)[2]), "=r"((r)[3])     \
                 : "r"(addr))

#define LDSM2(r, addr)                                                        \
    asm volatile("ldmatrix.sync.aligned.m8n8.x2.shared.b16 {%0,%1}, [%2];"    \
                 : "=r"((r)[0]), "=r"((r)[1])                                 \
                 : "r"(addr))

#define MMA16816(d, a, b0, b1)                                                \
    asm volatile("mma.sync.aligned.m16n8k16.row.col.f32.bf16.bf16.f32 "       \
                 "{%0,%1,%2,%3}, {%4,%5,%6,%7}, {%8,%9}, {%0,%1,%2,%3};"      \
                 : "+f"((d)[0]), "+f"((d)[1]), "+f"((d)[2]), "+f"((d)[3])     \
                 : "r"((a)[0]), "r"((a)[1]), "r"((a)[2]), "r"((a)[3]),        \
                   "r"(b0), "r"(b1))

constexpr int LDS_STRIDE = 136;  // 128 + 8 bf16 pad -> conflict-free smem

// fp32 x4 -> hi/lo bf16 pairs
__device__ __forceinline__ void split4(float4 v, uint2& hp, uint2& lp) {
    __nv_bfloat162 h0 = __float22bfloat162_rn(make_float2(v.x, v.y));
    __nv_bfloat162 h1 = __float22bfloat162_rn(make_float2(v.z, v.w));
    float2 h0f = __bfloat1622float2(h0);
    float2 h1f = __bfloat1622float2(h1);
    __nv_bfloat162 l0 = __float22bfloat162_rn(make_float2(v.x - h0f.x, v.y - h0f.y));
    __nv_bfloat162 l1 = __float22bfloat162_rn(make_float2(v.z - h1f.x, v.w - h1f.y));
    hp.x = *reinterpret_cast<uint32_t*>(&h0);
    hp.y = *reinterpret_cast<uint32_t*>(&h1);
    lp.x = *reinterpret_cast<uint32_t*>(&l0);
    lp.y = *reinterpret_cast<uint32_t*>(&l1);
}

// ---------------- single fused kernel: GEMM1 + EMA + gate + GEMM2 ----------------
// Grid: 128 CTAs = (b 0..3) x (16-row n-chunk, 32). Block: 512 (16 warps, 4/SMSP).
// Warp w owns primary cols [8w,8w+8), gating cols [128+8w,+8), GEMM2 cols [8w,+8).
// Per t: stage x tile -> GEMM1 (primary 3-pass, gating 1-pass) -> register EMA
// scan + sigmoid -> gated to smem (bf16 hi/lo) -> GEMM2 (3-pass) -> store out.
__global__ __launch_bounds__(512, 1)
void mamba_one(const float* __restrict__ x,
               const float* __restrict__ W_exp, const float* __restrict__ b_exp,
               const float* __restrict__ W_con, const float* __restrict__ b_con,
               float* __restrict__ out) {
    extern __shared__ char smem[];
    __nv_bfloat16* sWeHi = reinterpret_cast<__nv_bfloat16*>(smem);   // 256 rows
    __nv_bfloat16* sWeLo = sWeHi + 256 * LDS_STRIDE;                 // 128 rows (primary lo)
    __nv_bfloat16* sWcHi = sWeLo + 128 * LDS_STRIDE;                 // 128 rows
    __nv_bfloat16* sWcLo = sWcHi + 128 * LDS_STRIDE;                 // 128 rows
    __nv_bfloat16* sAhi  = sWcLo + 128 * LDS_STRIDE;                 // 16 rows
    __nv_bfloat16* sAlo  = sAhi + 16 * LDS_STRIDE;
    __nv_bfloat16* sGhi  = sAlo + 16 * LDS_STRIDE;                   // 16 rows
    __nv_bfloat16* sGlo  = sGhi + 16 * LDS_STRIDE;

    const int tid  = threadIdx.x;
    const int wid  = tid >> 5;          // 0..15
    const int lane = tid & 31;
    const int b    = blockIdx.x >> 5;
    const int n0   = (blockIdx.x & 31) * 16;

    // inline weight conversion (L2-served after first CTAs)
#pragma unroll 4
    for (int it = 0; it < 16; ++it) {           // W_exp: 8192 float4
        int i = tid + it * 512;
        int r = i >> 5, c4 = (i & 31) << 2;
        float4 v = *reinterpret_cast<const float4*>(W_exp + (size_t)r * 128 + c4);
        uint2 hp, lp;
        split4(v, hp, lp);
        int off = r * LDS_STRIDE + c4;
        *reinterpret_cast<uint2*>(sWeHi + off) = hp;
        if (r < 128) *reinterpret_cast<uint2*>(sWeLo + off) = lp;  // primary lo only
    }
#pragma unroll 4
    for (int it = 0; it < 8; ++it) {            // W_con: 4096 float4
        int i = tid + it * 512;
        int r = i >> 5, c4 = (i & 31) << 2;
        float4 v = *reinterpret_cast<const float4*>(W_con + (size_t)r * 128 + c4);
        uint2 hp, lp;
        split4(v, hp, lp);
        int off = r * LDS_STRIDE + c4;
        *reinterpret_cast<uint2*>(sWcHi + off) = hp;
        *reinterpret_cast<uint2*>(sWcLo + off) = lp;
    }

    // ldmatrix addresses
    uint32_t aHiAd, aLoAd, a2HiAd, a2LoAd;       // A frags (x4, 16 rows)
    uint32_t b1HiAd, b1LoAd, b1GtAd;             // GEMM1 B frags (x2, 8 cols)
    uint32_t b2HiAd, b2LoAd;                     // GEMM2 B frags (x2)
    {
        const uint32_t aoff = ((lane & 15) * LDS_STRIDE + (lane >> 4) * 8) * 2;
        aHiAd  = smem_u32(sAhi) + aoff;
        aLoAd  = smem_u32(sAlo) + aoff;
        a2HiAd = smem_u32(sGhi) + aoff;
        a2LoAd = smem_u32(sGlo) + aoff;
        // x2: lanes 0-15 address the two 8x8 tiles {8 cols, k0-7}, {8 cols, k8-15}
        int brow = 8 * wid + (lane & 7);
        int bkc  = ((lane >> 3) & 1) * 8;
        uint32_t boff = (brow * LDS_STRIDE + bkc) * 2;
        b1HiAd = smem_u32(sWeHi) + boff;                                 // primary hi
        b1GtAd = smem_u32(sWeHi) + boff + 128 * LDS_STRIDE * 2;          // gating hi
        b1LoAd = smem_u32(sWeLo) + boff;                                 // primary lo
        b2HiAd = smem_u32(sWcHi) + boff;
        b2LoAd = smem_u32(sWcLo) + boff;
    }

    const int gr = lane >> 2;
    const int gc = (lane & 3) * 2;
    float bp[2], bg[2], bo[2];
    bp[0] = b_exp[8 * wid + gc];
    bp[1] = b_exp[8 * wid + gc + 1];
    bg[0] = b_exp[128 + 8 * wid + gc];
    bg[1] = b_exp[128 + 8 * wid + gc + 1];
    bo[0] = b_con[8 * wid + gc];
    bo[1] = b_con[8 * wid + gc + 1];

    // EMA state (per-lane share of this warp's 16x8 gating block)
    float s[4] = {0.f, 0.f, 0.f, 0.f};

    // prefetch t = 0: 16x128 fp32 = 512 float4, 1 per thread
    float4 pf;
    {
        size_t rb = ((size_t)(b * Tdim) * Ndim + n0) * 128;
        int r = tid >> 5, c4 = (tid & 31) << 2;
        pf = *reinterpret_cast<const float4*>(x + rb + (size_t)r * 128 + c4);
    }

    for (int t = 0; t < Tdim; ++t) {
        // stage A tile (top barrier also protects last iter's sG reads)
        {
            int r = tid >> 5, c4 = (tid & 31) << 2;
            uint2 hp, lp;
            split4(pf, hp, lp);
            int off = r * LDS_STRIDE + c4;
            *reinterpret_cast<uint2*>(sAhi + off) = hp;
            *reinterpret_cast<uint2*>(sAlo + off) = lp;
        }
        __syncthreads();

        // prefetch next t (hidden under MMAs)
        if (t + 1 < Tdim) {
            size_t rb = ((size_t)(b * Tdim + t + 1) * Ndim + n0) * 128;
            int r = tid >> 5, c4 = (tid & 31) << 2;
            pf = *reinterpret_cast<const float4*>(x + rb + (size_t)r * 128 + c4);
        }

        // ---- GEMM1 ----
        float accP[4] = {0.f, 0.f, 0.f, 0.f};   // primary
        float accG[4] = {0.f, 0.f, 0.f, 0.f};   // gating

#pragma unroll
        for (int kk = 0; kk < 8; ++kk) {
            const uint32_t ko = kk * 32;
            uint32_t ah[4], al[4], bh[2], bl[2], bgt[2];
            LDSM4(ah, aHiAd + ko);
            LDSM2(bh, b1HiAd + ko);
            LDSM2(bgt, b1GtAd + ko);
            LDSM4(al, aLoAd + ko);
            LDSM2(bl, b1LoAd + ko);
            MMA16816(accP, ah, bh[0], bh[1]);    // primary hi*hi
            MMA16816(accP, ah, bl[0], bl[1]);    // primary hi*lo
            MMA16816(accP, al, bh[0], bh[1]);    // primary lo*hi
            MMA16816(accG, ah, bgt[0], bgt[1]);  // gating 1-pass
        }

        // ---- scan + gate + split into sG ----
        {
            float gt[4];
#pragma unroll
            for (int q = 0; q < 4; ++q) {
                float gv = accG[q] + bg[q & 1];
                s[q] = fmaf(0.9f, s[q], 0.1f * gv);
                float sig = 1.0f / (1.0f + __expf(-s[q]));
                gt[q] = (accP[q] + bp[q & 1]) * sig;
            }
            const int col = 8 * wid + gc;
#pragma unroll
            for (int h2 = 0; h2 < 2; ++h2) {
                float2 pr2 = make_float2(gt[h2 * 2], gt[h2 * 2 + 1]);
                __nv_bfloat162 hi2 = __float22bfloat162_rn(pr2);
                float2 hif = __bfloat1622float2(hi2);
                __nv_bfloat162 lo2 = __float22bfloat162_rn(
                    make_float2(pr2.x - hif.x, pr2.y - hif.y));
                int row = gr + h2 * 8;
                *reinterpret_cast<uint32_t*>(sGhi + row * LDS_STRIDE + col) =
                    *reinterpret_cast<uint32_t*>(&hi2);
                *reinterpret_cast<uint32_t*>(sGlo + row * LDS_STRIDE + col) =
                    *reinterpret_cast<uint32_t*>(&lo2);
            }
        }
        __syncthreads();   // sG complete, visible to all warps

        // ---- GEMM2: out rows = gated(16x128) * W_con^T + b_con ----
        float acc2[4] = {0.f, 0.f, 0.f, 0.f};
#pragma unroll
        for (int kk = 0; kk < 8; ++kk) {
            const uint32_t ko = kk * 32;
            uint32_t a2h[4], a2l[4], b2h[2], b2l[2];
            LDSM4(a2h, a2HiAd + ko);
            LDSM2(b2h, b2HiAd + ko);
            LDSM4(a2l, a2LoAd + ko);
            LDSM2(b2l, b2LoAd + ko);
            MMA16816(acc2, a2h, b2h[0], b2h[1]);
            MMA16816(acc2, a2h, b2l[0], b2l[1]);
            MMA16816(acc2, a2l, b2h[0], b2h[1]);
        }

        // direct store of out rows
        {
            size_t rowBase = (size_t)(b * Tdim + t) * Ndim + n0;
            const int col = 8 * wid + gc;
            float2 o0, o1;
            o0.x = acc2[0] + bo[0]; o0.y = acc2[1] + bo[1];
            o1.x = acc2[2] + bo[0]; o1.y = acc2[3] + bo[1];
            *reinterpret_cast<float2*>(&out[(rowBase + gr) * 128 + col])     = o0;
            *reinterpret_cast<float2*>(&out[(rowBase + gr + 8) * 128 + col]) = o1;
        }
    }
}

// ---------------- launch ----------------
extern "C" void kernel_launch(void* const* d_in, const int* in_sizes, int n_in,
                              void* d_out, int out_size) {
    const float* x     = (const float*)d_in[0];
    const float* W_exp = (const float*)d_in[1];
    const float* b_exp = (const float*)d_in[2];
    const float* W_con = (const float*)d_in[3];
    const float* b_con = (const float*)d_in[4];
    float* out = (float*)d_out;

    // smem: (256 + 128 + 128 + 128 + 4*16) rows * 136 * 2B = 191,488 bytes
    constexpr int SMEM = (256 + 128 + 128 + 128 + 64) * LDS_STRIDE * 2;
    cudaFuncSetAttribute(mamba_one, cudaFuncAttributeMaxDynamicSharedMemorySize, SMEM);

    mamba_one<<<Bdim * 32, 512, SMEM>>>(x, W_exp, b_exp, W_con, b_con, out);
}

// round 15
// speedup vs baseline: 1.0604x; 1.0604x over previous
#include <cuda_runtime.h>
#include <cuda_bf16.h>
#include <cstdint>
#include <math.h>

// ---------------- problem constants ----------------
constexpr int Bdim = 4;
constexpr int Tdim = 96;
constexpr int Ndim = 512;
constexpr int Hdim = 128;

// ---------------- helpers ----------------
__device__ __forceinline__ uint32_t smem_u32(const void* p) {
    uint32_t a;
    asm("{ .reg .u64 t; cvta.to.shared.u64 t, %1; cvt.u32.u64 %0, t; }"
        : "=r"(a) : "l"(p));
    return a;
}

#define LDSM4(r, addr)                                                        \
    asm volatile("ldmatrix.sync.aligned.m8n8.x4.shared.b16 {%0,%1,%2,%3}, [%4];" \
                 : "=r"((r)[0]), "=r"((r)[1]), "=r"((r)[2]), "=r"((r)[3])     \
                 : "r"(addr))

#define MMA16816(d, a, b0, b1)                                                \
    asm volatile("mma.sync.aligned.m16n8k16.row.col.f32.bf16.bf16.f32 "       \
                 "{%0,%1,%2,%3}, {%4,%5,%6,%7}, {%8,%9}, {%0,%1,%2,%3};"      \
                 : "+f"((d)[0]), "+f"((d)[1]), "+f"((d)[2]), "+f"((d)[3])     \
                 : "r"((a)[0]), "r"((a)[1]), "r"((a)[2]), "r"((a)[3]),        \
                   "r"(b0), "r"(b1))

constexpr int LDS_STRIDE = 136;  // 128 + 8 bf16 pad -> conflict-free smem

// fp32 x4 -> hi/lo bf16 pairs
__device__ __forceinline__ void split4(float4 v, uint2& hp, uint2& lp) {
    __nv_bfloat162 h0 = __float22bfloat162_rn(make_float2(v.x, v.y));
    __nv_bfloat162 h1 = __float22bfloat162_rn(make_float2(v.z, v.w));
    float2 h0f = __bfloat1622float2(h0);
    float2 h1f = __bfloat1622float2(h1);
    __nv_bfloat162 l0 = __float22bfloat162_rn(make_float2(v.x - h0f.x, v.y - h0f.y));
    __nv_bfloat162 l1 = __float22bfloat162_rn(make_float2(v.z - h1f.x, v.w - h1f.y));
    hp.x = *reinterpret_cast<uint32_t*>(&h0);
    hp.y = *reinterpret_cast<uint32_t*>(&h1);
    lp.x = *reinterpret_cast<uint32_t*>(&l0);
    lp.y = *reinterpret_cast<uint32_t*>(&l1);
}

// ---------------- single fused kernel: GEMM1 + EMA + gate + GEMM2 ----------------
// Grid: 128 CTAs = (b 0..3) x (16-row n-chunk, 32). Block: 256 (8 warps).
// Warp w owns primary cols [16w,+16), gating cols [128+16w,+16), GEMM2 cols [16w,+16).
// Split-bf16 3-pass products use SEPARATE accumulators (aHH/aHL/aLH), summed at
// the end -> 3x the independent MMA chains, covering HMMA dependent latency.
__global__ __launch_bounds__(256, 1)
void mamba_one(const float* __restrict__ x,
               const float* __restrict__ W_exp, const float* __restrict__ b_exp,
               const float* __restrict__ W_con, const float* __restrict__ b_con,
               float* __restrict__ out) {
    extern __shared__ char smem[];
    __nv_bfloat16* sWeHi = reinterpret_cast<__nv_bfloat16*>(smem);   // 256 rows
    __nv_bfloat16* sWeLo = sWeHi + 256 * LDS_STRIDE;                 // 128 rows (primary lo)
    __nv_bfloat16* sWcHi = sWeLo + 128 * LDS_STRIDE;                 // 128 rows
    __nv_bfloat16* sWcLo = sWcHi + 128 * LDS_STRIDE;                 // 128 rows
    __nv_bfloat16* sAhi  = sWcLo + 128 * LDS_STRIDE;                 // 16 rows
    __nv_bfloat16* sAlo  = sAhi + 16 * LDS_STRIDE;
    __nv_bfloat16* sGhi  = sAlo + 16 * LDS_STRIDE;                   // 16 rows
    __nv_bfloat16* sGlo  = sGhi + 16 * LDS_STRIDE;

    const int tid  = threadIdx.x;
    const int wid  = tid >> 5;
    const int lane = tid & 31;
    const int b    = blockIdx.x >> 5;
    const int n0   = (blockIdx.x & 31) * 16;

    // inline weight conversion (L2-served after first CTAs)
#pragma unroll 4
    for (int it = 0; it < 32; ++it) {           // W_exp: 8192 float4
        int i = tid + it * 256;
        int r = i >> 5, c4 = (i & 31) << 2;
        float4 v = *reinterpret_cast<const float4*>(W_exp + (size_t)r * 128 + c4);
        uint2 hp, lp;
        split4(v, hp, lp);
        int off = r * LDS_STRIDE + c4;
        *reinterpret_cast<uint2*>(sWeHi + off) = hp;
        if (r < 128) *reinterpret_cast<uint2*>(sWeLo + off) = lp;  // primary lo only
    }
#pragma unroll 4
    for (int it = 0; it < 16; ++it) {           // W_con: 4096 float4
        int i = tid + it * 256;
        int r = i >> 5, c4 = (i & 31) << 2;
        float4 v = *reinterpret_cast<const float4*>(W_con + (size_t)r * 128 + c4);
        uint2 hp, lp;
        split4(v, hp, lp);
        int off = r * LDS_STRIDE + c4;
        *reinterpret_cast<uint2*>(sWcHi + off) = hp;
        *reinterpret_cast<uint2*>(sWcLo + off) = lp;
    }

    // ldmatrix addresses
    uint32_t aHiAd, aLoAd, b1HiAd[2], b1LoAd;        // GEMM1
    uint32_t a2HiAd, a2LoAd, b2HiAd, b2LoAd;         // GEMM2
    {
        const uint32_t aoff = ((lane & 15) * LDS_STRIDE + (lane >> 4) * 8) * 2;
        aHiAd  = smem_u32(sAhi) + aoff;
        aLoAd  = smem_u32(sAlo) + aoff;
        a2HiAd = smem_u32(sGhi) + aoff;
        a2LoAd = smem_u32(sGlo) + aoff;
        int bc = ((lane >> 3) & 1) * 8;
        int brBase = 16 * wid + ((lane >> 4) << 3) + (lane & 7);
        b1HiAd[0] = smem_u32(sWeHi) + (brBase * LDS_STRIDE + bc) * 2;           // primary hi
        b1HiAd[1] = smem_u32(sWeHi) + ((128 + brBase) * LDS_STRIDE + bc) * 2;   // gating hi
        b1LoAd    = smem_u32(sWeLo) + (brBase * LDS_STRIDE + bc) * 2;           // primary lo
        b2HiAd    = smem_u32(sWcHi) + (brBase * LDS_STRIDE + bc) * 2;
        b2LoAd    = smem_u32(sWcLo) + (brBase * LDS_STRIDE + bc) * 2;
    }

    const int gr = lane >> 2;
    const int gc = (lane & 3) * 2;
    float bp[2][2], bg[2][2], bo[2][2];
#pragma unroll
    for (int jj = 0; jj < 2; ++jj) {
        bp[jj][0] = b_exp[16 * wid + jj * 8 + gc];
        bp[jj][1] = b_exp[16 * wid + jj * 8 + gc + 1];
        bg[jj][0] = b_exp[128 + 16 * wid + jj * 8 + gc];
        bg[jj][1] = b_exp[128 + 16 * wid + jj * 8 + gc + 1];
        bo[jj][0] = b_con[16 * wid + jj * 8 + gc];
        bo[jj][1] = b_con[16 * wid + jj * 8 + gc + 1];
    }

    // EMA state
    float s[2][4];
#pragma unroll
    for (int jj = 0; jj < 2; ++jj)
#pragma unroll
        for (int q = 0; q < 4; ++q) s[jj][q] = 0.0f;

    // prefetch t = 0: 16x128 fp32 = 512 float4, 2 per thread
    float4 pf[2];
    {
        size_t rb = ((size_t)(b * Tdim) * Ndim + n0) * 128;
#pragma unroll
        for (int it = 0; it < 2; ++it) {
            int i = tid + it * 256;
            int r = i >> 5, c4 = (i & 31) << 2;
            pf[it] = *reinterpret_cast<const float4*>(x + rb + (size_t)r * 128 + c4);
        }
    }

    for (int t = 0; t < Tdim; ++t) {
        // stage A tile (barrier also protects last iter's sG reads)
#pragma unroll
        for (int it = 0; it < 2; ++it) {
            int i = tid + it * 256;
            int r = i >> 5, c4 = (i & 31) << 2;
            uint2 hp, lp;
            split4(pf[it], hp, lp);
            int off = r * LDS_STRIDE + c4;
            *reinterpret_cast<uint2*>(sAhi + off) = hp;
            *reinterpret_cast<uint2*>(sAlo + off) = lp;
        }
        __syncthreads();

        // prefetch next t (hidden under MMAs)
        if (t + 1 < Tdim) {
            size_t rb = ((size_t)(b * Tdim + t + 1) * Ndim + n0) * 128;
#pragma unroll
            for (int it = 0; it < 2; ++it) {
                int i = tid + it * 256;
                int r = i >> 5, c4 = (i & 31) << 2;
                pf[it] = *reinterpret_cast<const float4*>(x + rb + (size_t)r * 128 + c4);
            }
        }

        // ---- GEMM1: separate accumulators per split-product ----
        float aHH[2][4], aHL[2][4], aLH[2][4], aG[2][4];
#pragma unroll
        for (int jj = 0; jj < 2; ++jj)
#pragma unroll
            for (int q = 0; q < 4; ++q) {
                aHH[jj][q] = 0.f; aHL[jj][q] = 0.f;
                aLH[jj][q] = 0.f; aG[jj][q]  = 0.f;
            }

#pragma unroll
        for (int kk = 0; kk < 8; ++kk) {
            const uint32_t ko = kk * 32;
            uint32_t ah[4], al[4], bh[2][4], bl[4];
            LDSM4(ah, aHiAd + ko);
            LDSM4(bh[0], b1HiAd[0] + ko);
            LDSM4(bh[1], b1HiAd[1] + ko);
            LDSM4(al, aLoAd + ko);
            LDSM4(bl, b1LoAd + ko);
#pragma unroll
            for (int jj = 0; jj < 2; ++jj) {
                const int wh = jj * 2;
                MMA16816(aHH[jj], ah, bh[0][wh], bh[0][wh + 1]);
                MMA16816(aG[jj],  ah, bh[1][wh], bh[1][wh + 1]);
                MMA16816(aHL[jj], ah, bl[wh],    bl[wh + 1]);
                MMA16816(aLH[jj], al, bh[0][wh], bh[0][wh + 1]);
            }
        }

        // ---- scan + gate + split into sG ----
#pragma unroll
        for (int jj = 0; jj < 2; ++jj) {
            float gt[4];
#pragma unroll
            for (int q = 0; q < 4; ++q) {
                float gv = aG[jj][q] + bg[jj][q & 1];
                s[jj][q] = fmaf(0.9f, s[jj][q], 0.1f * gv);
                float sig = 1.0f / (1.0f + __expf(-s[jj][q]));
                float pv = aHH[jj][q] + aHL[jj][q] + aLH[jj][q] + bp[jj][q & 1];
                gt[q] = pv * sig;
            }
            const int col = 16 * wid + jj * 8 + gc;
#pragma unroll
            for (int h2 = 0; h2 < 2; ++h2) {
                float2 pr2 = make_float2(gt[h2 * 2], gt[h2 * 2 + 1]);
                __nv_bfloat162 hi2 = __float22bfloat162_rn(pr2);
                float2 hif = __bfloat1622float2(hi2);
                __nv_bfloat162 lo2 = __float22bfloat162_rn(
                    make_float2(pr2.x - hif.x, pr2.y - hif.y));
                int row = gr + h2 * 8;
                *reinterpret_cast<uint32_t*>(sGhi + row * LDS_STRIDE + col) =
                    *reinterpret_cast<uint32_t*>(&hi2);
                *reinterpret_cast<uint32_t*>(sGlo + row * LDS_STRIDE + col) =
                    *reinterpret_cast<uint32_t*>(&lo2);
            }
        }
        __syncthreads();   // sG complete, visible to all warps

        // ---- GEMM2: separate accumulators per split-product ----
        float cHH[2][4], cHL[2][4], cLH[2][4];
#pragma unroll
        for (int jj = 0; jj < 2; ++jj)
#pragma unroll
            for (int q = 0; q < 4; ++q) {
                cHH[jj][q] = 0.f; cHL[jj][q] = 0.f; cLH[jj][q] = 0.f;
            }

#pragma unroll
        for (int kk = 0; kk < 8; ++kk) {
            const uint32_t ko = kk * 32;
            uint32_t a2h[4], a2l[4], b2h[4], b2l[4];
            LDSM4(a2h, a2HiAd + ko);
            LDSM4(b2h, b2HiAd + ko);
            LDSM4(a2l, a2LoAd + ko);
            LDSM4(b2l, b2LoAd + ko);
#pragma unroll
            for (int jj = 0; jj < 2; ++jj) {
                const int wh = jj * 2;
                MMA16816(cHH[jj], a2h, b2h[wh], b2h[wh + 1]);
                MMA16816(cHL[jj], a2h, b2l[wh], b2l[wh + 1]);
                MMA16816(cLH[jj], a2l, b2h[wh], b2h[wh + 1]);
            }
        }

        // direct store of out rows
        {
            size_t rowBase = (size_t)(b * Tdim + t) * Ndim + n0;
#pragma unroll
            for (int jj = 0; jj < 2; ++jj) {
                const int col = 16 * wid + jj * 8 + gc;
                float2 o0, o1;
                o0.x = cHH[jj][0] + cHL[jj][0] + cLH[jj][0] + bo[jj][0];
                o0.y = cHH[jj][1] + cHL[jj][1] + cLH[jj][1] + bo[jj][1];
                o1.x = cHH[jj][2] + cHL[jj][2] + cLH[jj][2] + bo[jj][0];
                o1.y = cHH[jj][3] + cHL[jj][3] + cLH[jj][3] + bo[jj][1];
                *reinterpret_cast<float2*>(&out[(rowBase + gr) * 128 + col])     = o0;
                *reinterpret_cast<float2*>(&out[(rowBase + gr + 8) * 128 + col]) = o1;
            }
        }
    }
}

// ---------------- launch ----------------
extern "C" void kernel_launch(void* const* d_in, const int* in_sizes, int n_in,
                              void* d_out, int out_size) {
    const float* x     = (const float*)d_in[0];
    const float* W_exp = (const float*)d_in[1];
    const float* b_exp = (const float*)d_in[2];
    const float* W_con = (const float*)d_in[3];
    const float* b_con = (const float*)d_in[4];
    float* out = (float*)d_out;

    // smem: (256 + 128 + 128 + 128 + 4*16) rows * 136 * 2B = 191,488 bytes
    constexpr int SMEM = (256 + 128 + 128 + 128 + 64) * LDS_STRIDE * 2;
    cudaFuncSetAttribute(mamba_one, cudaFuncAttributeMaxDynamicSharedMemorySize, SMEM);

    mamba_one<<<Bdim * 32, 256, SMEM>>>(x, W_exp, b_exp, W_con, b_con, out);
}

// round 17
// speedup vs baseline: 1.1206x; 1.0567x over previous
#include <cuda_runtime.h>
#include <cuda_bf16.h>
#include <cstdint>
#include <math.h>

// ---------------- problem constants ----------------
constexpr int Bdim = 4;
constexpr int Tdim = 96;
constexpr int Ndim = 512;
constexpr int Hdim = 128;

// ---------------- helpers ----------------
__device__ __forceinline__ uint32_t smem_u32(const void* p) {
    uint32_t a;
    asm("{ .reg .u64 t; cvta.to.shared.u64 t, %1; cvt.u32.u64 %0, t; }"
        : "=r"(a) : "l"(p));
    return a;
}

#define LDSM4(r, addr)                                                        \
    asm volatile("ldmatrix.sync.aligned.m8n8.x4.shared.b16 {%0,%1,%2,%3}, [%4];" \
                 : "=r"((r)[0]), "=r"((r)[1]), "=r"((r)[2]), "=r"((r)[3])     \
                 : "r"(addr))

#define MMA16816(d, a, b0, b1)                                                \
    asm volatile("mma.sync.aligned.m16n8k16.row.col.f32.bf16.bf16.f32 "       \
                 "{%0,%1,%2,%3}, {%4,%5,%6,%7}, {%8,%9}, {%0,%1,%2,%3};"      \
                 : "+f"((d)[0]), "+f"((d)[1]), "+f"((d)[2]), "+f"((d)[3])     \
                 : "r"((a)[0]), "r"((a)[1]), "r"((a)[2]), "r"((a)[3]),        \
                   "r"(b0), "r"(b1))

constexpr int LDS_STRIDE = 136;  // 128 + 8 bf16 pad -> conflict-free smem

// fp32 x4 -> hi/lo bf16 pairs
__device__ __forceinline__ void split4(float4 v, uint2& hp, uint2& lp) {
    __nv_bfloat162 h0 = __float22bfloat162_rn(make_float2(v.x, v.y));
    __nv_bfloat162 h1 = __float22bfloat162_rn(make_float2(v.z, v.w));
    float2 h0f = __bfloat1622float2(h0);
    float2 h1f = __bfloat1622float2(h1);
    __nv_bfloat162 l0 = __float22bfloat162_rn(make_float2(v.x - h0f.x, v.y - h0f.y));
    __nv_bfloat162 l1 = __float22bfloat162_rn(make_float2(v.z - h1f.x, v.w - h1f.y));
    hp.x = *reinterpret_cast<uint32_t*>(&h0);
    hp.y = *reinterpret_cast<uint32_t*>(&h1);
    lp.x = *reinterpret_cast<uint32_t*>(&l0);
    lp.y = *reinterpret_cast<uint32_t*>(&l1);
}

// ---------------- single fused kernel, software-pipelined over t ----------------
// Grid: 128 CTAs = (b 0..3) x (16-row n-chunk, 32). Block: 256 (8 warps).
// Steady state per t (ONE barrier): stage A(t+1)[par1] | bar | { GEMM2(t)[sG par]
// INTERLEAVED with GEMM1(t+1)[sA par1] } | store out(t) | scan(t+1) -> sG[par1].
// sA and sG are ping-pong double-buffered; 6 independent MMA chains per warp.
__global__ __launch_bounds__(256, 1)
void mamba_one(const float* __restrict__ x,
               const float* __restrict__ W_exp, const float* __restrict__ b_exp,
               const float* __restrict__ W_con, const float* __restrict__ b_con,
               float* __restrict__ out) {
    extern __shared__ char smem[];
    __nv_bfloat16* sWeHi = reinterpret_cast<__nv_bfloat16*>(smem);   // 256 rows
    __nv_bfloat16* sWeLo = sWeHi + 256 * LDS_STRIDE;                 // 128 rows (primary lo)
    __nv_bfloat16* sWcHi = sWeLo + 128 * LDS_STRIDE;                 // 128 rows
    __nv_bfloat16* sWcLo = sWcHi + 128 * LDS_STRIDE;                 // 128 rows
    __nv_bfloat16* sA    = sWcLo + 128 * LDS_STRIDE;                 // 2 bufs x 32 rows
    __nv_bfloat16* sG    = sA + 64 * LDS_STRIDE;                     // 2 bufs x 32 rows

    const int tid  = threadIdx.x;
    const int wid  = tid >> 5;
    const int lane = tid & 31;
    const int b    = blockIdx.x >> 5;
    const int n0   = (blockIdx.x & 31) * 16;

    // inline weight conversion (L2-served after first CTAs)
#pragma unroll 4
    for (int it = 0; it < 32; ++it) {           // W_exp: 8192 float4
        int i = tid + it * 256;
        int r = i >> 5, c4 = (i & 31) << 2;
        float4 v = *reinterpret_cast<const float4*>(W_exp + (size_t)r * 128 + c4);
        uint2 hp, lp;
        split4(v, hp, lp);
        int off = r * LDS_STRIDE + c4;
        *reinterpret_cast<uint2*>(sWeHi + off) = hp;
        if (r < 128) *reinterpret_cast<uint2*>(sWeLo + off) = lp;
    }
#pragma unroll 4
    for (int it = 0; it < 16; ++it) {           // W_con: 4096 float4
        int i = tid + it * 256;
        int r = i >> 5, c4 = (i & 31) << 2;
        float4 v = *reinterpret_cast<const float4*>(W_con + (size_t)r * 128 + c4);
        uint2 hp, lp;
        split4(v, hp, lp);
        int off = r * LDS_STRIDE + c4;
        *reinterpret_cast<uint2*>(sWcHi + off) = hp;
        *reinterpret_cast<uint2*>(sWcLo + off) = lp;
    }

    // ldmatrix addresses (per parity for sA/sG)
    uint32_t aHiAd[2], aLoAd[2], a2HiAd[2], a2LoAd[2];
    uint32_t b1HiAd[2], b1LoAd, b2HiAd, b2LoAd;
    {
        const uint32_t aoff = ((lane & 15) * LDS_STRIDE + (lane >> 4) * 8) * 2;
        const uint32_t sAb = smem_u32(sA), sGb = smem_u32(sG);
        constexpr uint32_t BUFB = 32 * LDS_STRIDE * 2;   // bytes per parity buf
        constexpr uint32_t LOB  = 16 * LDS_STRIDE * 2;   // hi->lo offset
#pragma unroll
        for (int p = 0; p < 2; ++p) {
            aHiAd[p]  = sAb + p * BUFB + aoff;
            aLoAd[p]  = aHiAd[p] + LOB;
            a2HiAd[p] = sGb + p * BUFB + aoff;
            a2LoAd[p] = a2HiAd[p] + LOB;
        }
        int bc = ((lane >> 3) & 1) * 8;
        int brBase = 16 * wid + ((lane >> 4) << 3) + (lane & 7);
        b1HiAd[0] = smem_u32(sWeHi) + (brBase * LDS_STRIDE + bc) * 2;           // primary hi
        b1HiAd[1] = smem_u32(sWeHi) + ((128 + brBase) * LDS_STRIDE + bc) * 2;   // gating hi
        b1LoAd    = smem_u32(sWeLo) + (brBase * LDS_STRIDE + bc) * 2;           // primary lo
        b2HiAd    = smem_u32(sWcHi) + (brBase * LDS_STRIDE + bc) * 2;
        b2LoAd    = smem_u32(sWcLo) + (brBase * LDS_STRIDE + bc) * 2;
    }

    const int gr = lane >> 2;
    const int gc = (lane & 3) * 2;
    float bp[2][2], bg[2][2], bo[2][2];
#pragma unroll
    for (int jj = 0; jj < 2; ++jj) {
        bp[jj][0] = b_exp[16 * wid + jj * 8 + gc];
        bp[jj][1] = b_exp[16 * wid + jj * 8 + gc + 1];
        bg[jj][0] = b_exp[128 + 16 * wid + jj * 8 + gc];
        bg[jj][1] = b_exp[128 + 16 * wid + jj * 8 + gc + 1];
        bo[jj][0] = b_con[16 * wid + jj * 8 + gc];
        bo[jj][1] = b_con[16 * wid + jj * 8 + gc + 1];
    }

    // EMA state
    float s[2][4];
#pragma unroll
    for (int jj = 0; jj < 2; ++jj)
#pragma unroll
        for (int q = 0; q < 4; ++q) s[jj][q] = 0.0f;

    // ---- staging helpers ----
    auto stageA = [&](int par, const float4* pfp) {
#pragma unroll
        for (int it = 0; it < 2; ++it) {
            int i = tid + it * 256;
            int r = i >> 5, c4 = (i & 31) << 2;
            uint2 hp, lp;
            split4(pfp[it], hp, lp);
            int off = (par * 32 + r) * LDS_STRIDE + c4;
            *reinterpret_cast<uint2*>(sA + off) = hp;
            *reinterpret_cast<uint2*>(sA + off + 16 * LDS_STRIDE) = lp;
        }
    };
    auto prefetchX = [&](int t, float4* pfp) {
        size_t rb = ((size_t)(b * Tdim + t) * Ndim + n0) * 128;
#pragma unroll
        for (int it = 0; it < 2; ++it) {
            int i = tid + it * 256;
            int r = i >> 5, c4 = (i & 31) << 2;
            pfp[it] = *reinterpret_cast<const float4*>(x + rb + (size_t)r * 128 + c4);
        }
    };
    // scan + gate + split into sG[par]; consumes accP/accG
    auto scanGate = [&](int par, float (*accP)[4], float (*accG)[4]) {
#pragma unroll
        for (int jj = 0; jj < 2; ++jj) {
            float gt[4];
#pragma unroll
            for (int q = 0; q < 4; ++q) {
                float gv = accG[jj][q] + bg[jj][q & 1];
                s[jj][q] = fmaf(0.9f, s[jj][q], 0.1f * gv);
                float sig = 1.0f / (1.0f + __expf(-s[jj][q]));
                gt[q] = (accP[jj][q] + bp[jj][q & 1]) * sig;
            }
            const int col = 16 * wid + jj * 8 + gc;
#pragma unroll
            for (int h2 = 0; h2 < 2; ++h2) {
                float2 pr2 = make_float2(gt[h2 * 2], gt[h2 * 2 + 1]);
                __nv_bfloat162 hi2 = __float22bfloat162_rn(pr2);
                float2 hif = __bfloat1622float2(hi2);
                __nv_bfloat162 lo2 = __float22bfloat162_rn(
                    make_float2(pr2.x - hif.x, pr2.y - hif.y));
                int row = par * 32 + gr + h2 * 8;
                *reinterpret_cast<uint32_t*>(sG + row * LDS_STRIDE + col) =
                    *reinterpret_cast<uint32_t*>(&hi2);
                *reinterpret_cast<uint32_t*>(sG + (row + 16) * LDS_STRIDE + col) =
                    *reinterpret_cast<uint32_t*>(&lo2);
            }
        }
    };
    auto storeOut = [&](int t, float (*accO)[4]) {
        size_t rowBase = (size_t)(b * Tdim + t) * Ndim + n0;
#pragma unroll
        for (int jj = 0; jj < 2; ++jj) {
            const int col = 16 * wid + jj * 8 + gc;
            float2 o0, o1;
            o0.x = accO[jj][0] + bo[jj][0]; o0.y = accO[jj][1] + bo[jj][1];
            o1.x = accO[jj][2] + bo[jj][0]; o1.y = accO[jj][3] + bo[jj][1];
            *reinterpret_cast<float2*>(&out[(rowBase + gr) * 128 + col])     = o0;
            *reinterpret_cast<float2*>(&out[(rowBase + gr + 8) * 128 + col]) = o1;
        }
    };

    // ---- preamble: t = 0 GEMM1 + scan ----
    float4 pf[2];
    prefetchX(0, pf);
    stageA(0, pf);
    __syncthreads();               // publishes weights + A(0)
    prefetchX(1, pf);
    {
        float accP[2][4] = {}, accG[2][4] = {};
#pragma unroll
        for (int kk = 0; kk < 8; ++kk) {
            const uint32_t ko = kk * 32;
            uint32_t ah[4], al[4], bh[2][4], bl[4];
            LDSM4(ah, aHiAd[0] + ko);
            LDSM4(bh[0], b1HiAd[0] + ko);
            LDSM4(bh[1], b1HiAd[1] + ko);
            LDSM4(al, aLoAd[0] + ko);
            LDSM4(bl, b1LoAd + ko);
#pragma unroll
            for (int jj = 0; jj < 2; ++jj) {
                const int wh = jj * 2;
                MMA16816(accP[jj], ah, bh[0][wh], bh[0][wh + 1]);
                MMA16816(accG[jj], ah, bh[1][wh], bh[1][wh + 1]);
                MMA16816(accP[jj], ah, bl[wh],    bl[wh + 1]);
                MMA16816(accP[jj], al, bh[0][wh], bh[0][wh + 1]);
            }
        }
        scanGate(0, accP, accG);
    }

    // ---- steady state: t = 0..94 ----
    for (int t = 0; t < Tdim - 1; ++t) {
        const int par  = t & 1;
        const int par1 = (t + 1) & 1;

        stageA(par1, pf);          // pf holds x(t+1)
        __syncthreads();           // publishes A(t+1) and sG(t)

        if (t + 2 < Tdim) prefetchX(t + 2, pf);

        float accP[2][4] = {}, accG[2][4] = {}, accO[2][4] = {};
#pragma unroll
        for (int kk = 0; kk < 8; ++kk) {
            const uint32_t ko = kk * 32;
            uint32_t ah[4], al[4], bh[2][4], bl[4];
            uint32_t g2ah[4], g2al[4], g2bh[4], g2bl[4];
            LDSM4(g2ah, a2HiAd[par] + ko);
            LDSM4(g2bh, b2HiAd + ko);
            LDSM4(ah, aHiAd[par1] + ko);
            LDSM4(bh[0], b1HiAd[0] + ko);
            LDSM4(bh[1], b1HiAd[1] + ko);
            LDSM4(g2al, a2LoAd[par] + ko);
            LDSM4(g2bl, b2LoAd + ko);
            LDSM4(al, aLoAd[par1] + ko);
            LDSM4(bl, b1LoAd + ko);
#pragma unroll
            for (int jj = 0; jj < 2; ++jj) {
                const int wh = jj * 2;
                // interleave the two GEMMs' independent chains
                MMA16816(accO[jj], g2ah, g2bh[wh], g2bh[wh + 1]);
                MMA16816(accP[jj], ah,   bh[0][wh], bh[0][wh + 1]);
                MMA16816(accG[jj], ah,   bh[1][wh], bh[1][wh + 1]);
                MMA16816(accO[jj], g2ah, g2bl[wh], g2bl[wh + 1]);
                MMA16816(accP[jj], ah,   bl[wh],    bl[wh + 1]);
                MMA16816(accO[jj], g2al, g2bh[wh], g2bh[wh + 1]);
                MMA16816(accP[jj], al,   bh[0][wh], bh[0][wh + 1]);
            }
        }

        storeOut(t, accO);
        scanGate(par1, accP, accG);
    }

    // ---- epilogue: GEMM2(95) ----
    __syncthreads();               // publishes sG(95)
    {
        const int par = (Tdim - 1) & 1;
        float accO[2][4] = {};
#pragma unroll
        for (int kk = 0; kk < 8; ++kk) {
            const uint32_t ko = kk * 32;
            uint32_t g2ah[4], g2al[4], g2bh[4], g2bl[4];
            LDSM4(g2ah, a2HiAd[par] + ko);
            LDSM4(g2bh, b2HiAd + ko);
            LDSM4(g2al, a2LoAd[par] + ko);
            LDSM4(g2bl, b2LoAd + ko);
#pragma unroll
            for (int jj = 0; jj < 2; ++jj) {
                const int wh = jj * 2;
                MMA16816(accO[jj], g2ah, g2bh[wh], g2bh[wh + 1]);
                MMA16816(accO[jj], g2ah, g2bl[wh], g2bl[wh + 1]);
                MMA16816(accO[jj], g2al, g2bh[wh], g2bh[wh + 1]);
            }
        }
        storeOut(Tdim - 1, accO);
    }
}

// ---------------- launch ----------------
extern "C" void kernel_launch(void* const* d_in, const int* in_sizes, int n_in,
                              void* d_out, int out_size) {
    const float* x     = (const float*)d_in[0];
    const float* W_exp = (const float*)d_in[1];
    const float* b_exp = (const float*)d_in[2];
    const float* W_con = (const float*)d_in[3];
    const float* b_con = (const float*)d_in[4];
    float* out = (float*)d_out;

    // smem: (256+128+128+128 + 64 + 64) rows * 136 * 2B = 208,896 bytes
    constexpr int SMEM = (256 + 128 + 128 + 128 + 64 + 64) * LDS_STRIDE * 2;
    cudaFuncSetAttribute(mamba_one, cudaFuncAttributeMaxDynamicSharedMemorySize, SMEM);

    mamba_one<<<Bdim * 32, 256, SMEM>>>(x, W_exp, b_exp, W_con, b_con, out);
}